// round 3
// baseline (speedup 1.0000x reference)
#include <cuda_runtime.h>
#include <cfloat>

// N=8192 tokens, K=4096, D=1024.
//   idx[n] = argmax_k x[n,k]  (first-occurrence tie-break)
//   out[n,d] = W[d, idx[n]]   (column gather from W [D,K] row-major)
//
// K1: fused grid — 8192 blocks do per-token argmax -> g_idx, 1024 blocks
//     transpose W -> g_Wt [K,D] (independent work, overlapped in one launch;
//     transpose blocks at grid tail so Wt is hot in L2 when K2 starts).
// K2: row gather out[n,:] = g_Wt[idx[n],:], 8 rows/block for MLP=8.

#define NTOK 8192
#define KDIM 4096
#define DDIM 1024

// scratch (allocation-free rule: __device__ globals)
__device__ float g_Wt[(size_t)KDIM * DDIM];   // 16 MB
__device__ int   g_idx[NTOK];

#define TP_TILE   64
#define TP_BLOCKS ((KDIM / TP_TILE) * (DDIM / TP_TILE))   // 64 * 16 = 1024

// ---------------- K1: fused argmax + transpose ----------------
__global__ void __launch_bounds__(256) fused_argmax_transpose_kernel(
    const float* __restrict__ x, const float* __restrict__ W)
{
    const int bid = blockIdx.x;
    const int tid = threadIdx.x;

    if (bid < NTOK) {
        // ---- per-token argmax over x[bid, :] ----
        const int n = bid;
        const float4* xr = reinterpret_cast<const float4*>(x + (size_t)n * KDIM);
        float best = -FLT_MAX;
        int   bi   = 0x7fffffff;

        #pragma unroll
        for (int it = 0; it < (KDIM / 4) / 256; ++it) {
            int c = tid + it * 256;
            float4 v = xr[c];
            int base = c * 4;
            if (v.x > best) { best = v.x; bi = base + 0; }
            if (v.y > best) { best = v.y; bi = base + 1; }
            if (v.z > best) { best = v.z; bi = base + 2; }
            if (v.w > best) { best = v.w; bi = base + 3; }
        }

        // warp reduce (smaller index wins ties)
        #pragma unroll
        for (int off = 16; off > 0; off >>= 1) {
            float ov = __shfl_down_sync(0xffffffffu, best, off);
            int   oi = __shfl_down_sync(0xffffffffu, bi,   off);
            if (ov > best || (ov == best && oi < bi)) { best = ov; bi = oi; }
        }

        // block reduce across 8 warps
        __shared__ float s_val[8];
        __shared__ int   s_idx[8];
        int warp = tid >> 5;
        int lane = tid & 31;
        if (lane == 0) { s_val[warp] = best; s_idx[warp] = bi; }
        __syncthreads();
        if (warp == 0) {
            best = (lane < 8) ? s_val[lane] : -FLT_MAX;
            bi   = (lane < 8) ? s_idx[lane] : 0x7fffffff;
            #pragma unroll
            for (int off = 4; off > 0; off >>= 1) {
                float ov = __shfl_down_sync(0xffffffffu, best, off);
                int   oi = __shfl_down_sync(0xffffffffu, bi,   off);
                if (ov > best || (ov == best && oi < bi)) { best = ov; bi = oi; }
            }
            if (lane == 0) g_idx[n] = bi;
        }
    } else {
        // ---- transpose one 64x64 tile of W [D,K] -> g_Wt [K,D] ----
        __shared__ float t[TP_TILE][TP_TILE + 1];
        const int tile = bid - NTOK;                 // 0 .. 1023
        const int k0 = (tile % (KDIM / TP_TILE)) * TP_TILE;
        const int d0 = (tile / (KDIM / TP_TILE)) * TP_TILE;
        const int tx = tid & 15;     // float4 lane along fast dim
        const int ty = tid >> 4;     // row 0..15

        #pragma unroll
        for (int i = 0; i < 4; ++i) {
            int r = ty + 16 * i;     // d offset within tile
            float4 v = *reinterpret_cast<const float4*>(
                W + (size_t)(d0 + r) * KDIM + (k0 + 4 * tx));
            t[r][4 * tx + 0] = v.x;
            t[r][4 * tx + 1] = v.y;
            t[r][4 * tx + 2] = v.z;
            t[r][4 * tx + 3] = v.w;
        }
        __syncthreads();

        #pragma unroll
        for (int i = 0; i < 4; ++i) {
            int r = ty + 16 * i;     // k offset within tile
            float4 v;
            v.x = t[4 * tx + 0][r];
            v.y = t[4 * tx + 1][r];
            v.z = t[4 * tx + 2][r];
            v.w = t[4 * tx + 3][r];
            *reinterpret_cast<float4*>(
                g_Wt + (size_t)(k0 + r) * DDIM + (d0 + 4 * tx)) = v;
        }
    }
}

// ---------------- K2: row gather, 8 rows per block (MLP=8) ----------------
#define G_ROWS 8
__global__ void __launch_bounds__(256) gather_kernel(float* __restrict__ out)
{
    const int n0  = blockIdx.x * G_ROWS;
    const int tid = threadIdx.x;

    // broadcast the 8 indices via shared memory (one tiny coalesced load)
    __shared__ int s_idx[G_ROWS];
    if (tid < G_ROWS) s_idx[tid] = g_idx[n0 + tid];
    __syncthreads();

    // 8 independent row loads (front-batched), then 8 stores
    float4 v[G_ROWS];
    #pragma unroll
    for (int i = 0; i < G_ROWS; ++i) {
        const float4* src =
            reinterpret_cast<const float4*>(g_Wt + (size_t)s_idx[i] * DDIM);
        v[i] = src[tid];
    }
    #pragma unroll
    for (int i = 0; i < G_ROWS; ++i) {
        float4* dst = reinterpret_cast<float4*>(out + (size_t)(n0 + i) * DDIM);
        dst[tid] = v[i];
    }
}

extern "C" void kernel_launch(void* const* d_in, const int* in_sizes, int n_in,
                              void* d_out, int out_size) {
    const float* x = (const float*)d_in[0];   // [N, K]
    const float* W = (const float*)d_in[1];   // [D, K]
    float* out = (float*)d_out;               // [N, D]

    fused_argmax_transpose_kernel<<<NTOK + TP_BLOCKS, 256>>>(x, W);
    gather_kernel<<<NTOK / G_ROWS, 256>>>(out);
}